// round 16
// baseline (speedup 1.0000x reference)
#include <cuda_runtime.h>
#include <math.h>

#define HDIM 2048
#define SQ   2048
#define NHEAD 32
#define NKVH  8
#define HD    64
#define IDIM  4096
#define NE    8

// ------------------------- scratch (static, no allocs) -------------------------
__device__ float g_xn1[SQ*HDIM];
__device__ float g_q[SQ*NHEAD*HD];
__device__ float g_k[SQ*NKVH*HD];
__device__ float g_v[SQ*NKVH*HD];
__device__ float g_ctx[SQ*NHEAD*HD];
__device__ float g_resid1[SQ*HDIM];
__device__ float g_xn2[SQ*HDIM];
__device__ float g_rlog[SQ*NE];
__device__ int   g_tok2e[SQ*2];
__device__ float g_tok2w[SQ*2];
__device__ int   g_rows[SQ*2];
__device__ float g_roww[SQ*2];
__device__ int   g_cnt[NE];
__device__ int   g_off[NE+1];
__device__ int   g_cur[NE];
__device__ float g_xg[SQ*2*HDIM];
__device__ float g_b1[SQ*2*IDIM];
__device__ int   g_pos64;
__device__ float g_posf[SQ];

// tf32 round-to-nearest
__device__ __forceinline__ float f2tf32rn(float f) {
    unsigned r;
    asm("cvt.rna.tf32.f32 %0, %1;" : "=r"(r) : "f"(f));
    return __uint_as_float(r);
}

// B-operand arrives raw via cp.async -> HW tf32-truncates (multiplicative mean
// shrink ~3.52e-4). Compensate the accumulator once in the epilogue.
#define TRUNC_COMP 1.000352f

// ------------------------- position width detection (+ MoE counter reset) ----
__global__ void posdetect_kernel(const unsigned int* __restrict__ p) {
    __shared__ int ok;
    if (threadIdx.x == 0) ok = 1;
    __syncthreads();
    int bad = 0;
    for (int i = threadIdx.x; i < SQ/2; i += blockDim.x)
        if (p[2*i+1] != 0u) bad = 1;
    if (bad) atomicAnd(&ok, 0);
    __syncthreads();
    if (threadIdx.x == 0) g_pos64 = ok;
    if (threadIdx.x < NE) { g_cnt[threadIdx.x] = 0; g_cur[threadIdx.x] = 0; }
}

__global__ void posconv_kernel(const void* __restrict__ p) {
    int i = blockIdx.x*blockDim.x + threadIdx.x;
    if (i >= SQ) return;
    long long v = g_pos64 ? ((const long long*)p)[i]
                          : (long long)((const int*)p)[i];
    g_posf[i] = (float)v;
}

// ------------------------- RMSNorm -------------------------
__global__ void rmsnorm_kernel(const float* __restrict__ x, const float* __restrict__ w,
                               float* __restrict__ o, int do_round) {
    int row = blockIdx.x;
    const float* xr = x + (size_t)row*HDIM;
    float s = 0.f;
    for (int c = threadIdx.x; c < HDIM; c += blockDim.x) { float v = xr[c]; s += v*v; }
    __shared__ float red[8];
    for (int off = 16; off; off >>= 1) s += __shfl_xor_sync(0xffffffffu, s, off);
    int warp = threadIdx.x >> 5, lane = threadIdx.x & 31;
    if (lane == 0) red[warp] = s;
    __syncthreads();
    if (warp == 0) {
        float t = (lane < 8) ? red[lane] : 0.f;
        for (int off = 4; off; off >>= 1) t += __shfl_xor_sync(0xffffffffu, t, off);
        if (lane == 0) red[0] = t;
    }
    __syncthreads();
    float inv = rsqrtf(red[0] / (float)HDIM + 1e-5f);
    float* orow = o + (size_t)row*HDIM;
    if (do_round) {
        for (int c = threadIdx.x; c < HDIM; c += blockDim.x)
            orow[c] = f2tf32rn(xr[c] * inv * w[c]);
    } else {
        for (int c = threadIdx.x; c < HDIM; c += blockDim.x)
            orow[c] = xr[c] * inv * w[c];
    }
}

// ------------------------- TF32 HMMA GEMM (NT), cp.async BK32, 3-stage -------------------------
#define BM 128
#define BN 128
#define BK 32
#define STAGEB 32768           // bytes per stage (A 16KB + B 16KB)
#define NSTAGE 3
#define SMEMTC (NSTAGE*STAGEB)

__device__ __forceinline__ void mma_tf32(float c[4], float2 alo, float2 ahi, float2 b) {
    asm volatile(
        "mma.sync.aligned.m16n8k8.row.col.f32.tf32.tf32.f32 "
        "{%0,%1,%2,%3}, {%4,%5,%6,%7}, {%8,%9}, {%0,%1,%2,%3};\n"
        : "+f"(c[0]), "+f"(c[1]), "+f"(c[2]), "+f"(c[3])
        : "r"(__float_as_uint(alo.x)), "r"(__float_as_uint(ahi.x)),
          "r"(__float_as_uint(alo.y)), "r"(__float_as_uint(ahi.y)),
          "r"(__float_as_uint(b.x)),   "r"(__float_as_uint(b.y)));
}

__device__ __forceinline__ unsigned smem_u32(const void* p) {
    unsigned a;
    asm("{ .reg .u64 t; cvta.to.shared.u64 t, %1; cvt.u32.u64 %0, t; }" : "=r"(a) : "l"(p));
    return a;
}

__device__ __forceinline__ void cpa16(unsigned dst, const float* src, int bytes) {
    asm volatile("cp.async.cg.shared.global [%0], [%1], 16, %2;"
                 :: "r"(dst), "l"(src), "r"(bytes) : "memory");
}
__device__ __forceinline__ void cpa_commit() {
    asm volatile("cp.async.commit_group;" ::: "memory");
}
__device__ __forceinline__ void cpa_wait1() {
    asm volatile("cp.async.wait_group 1;" ::: "memory");
}

// one BK32 stage: 128 rows x 8 chunks x 2 operands = 2048 chunks, 8/thread
__device__ __forceinline__ void tcga_issue(
    unsigned sbase, const float* __restrict__ A, const float* __restrict__ B,
    int m0, int Mend, int n0, int N, int K, int ks, int tid)
{
#pragma unroll
    for (int i = 0; i < 8; i++) {
        int idx = tid + i*256;
        int isB = idx >> 10;
        int l = idx & 1023;
        int r = l >> 3, c = l & 7;
        const float* src;
        int bytes;
        if (!isB) { src = A + (size_t)(m0 + r)*K + ks + (c << 2); bytes = (m0 + r < Mend) ? 16 : 0; }
        else      { src = B + (size_t)(n0 + r)*K + ks + (c << 2); bytes = (n0 + r < N)    ? 16 : 0; }
        int csw = c ^ ((r & 1) << 2);
        unsigned dst = sbase + (isB ? 16384u : 0u) + (unsigned)(r*128 + csw*16);
        cpa16(dst, src, bytes);
    }
}

// EPI 0: C = acc (+R); optional C2 mirrors C (o-proj residual dual-write).
// EPI 2: MoE w2 output scatter: token = g_rows[row], w = g_roww[row];
//        atomicAdd(&C[token*N+col], w*acc).
template<int EPI>
__device__ __forceinline__ void gemm_tf32_body(
    const float* __restrict__ A, const float* __restrict__ B,
    float* __restrict__ C, const float* __restrict__ R, float* __restrict__ C2,
    int m0, int Mend, int n0, int N, int K)
{
    extern __shared__ float smtc[];
    unsigned sb0 = smem_u32(smtc);
    int tid = threadIdx.x;
    int lane = tid & 31, wid = tid >> 5;
    int wm = (wid & 1) * 64;
    int wn = (wid >> 1) * 32;
    int tig = lane & 3, grp = lane >> 2;
    int swl = (grp & 1) << 2;

    float acc[4][4][4];
#pragma unroll
    for (int i = 0; i < 4; i++)
#pragma unroll
        for (int j = 0; j < 4; j++)
#pragma unroll
            for (int r = 0; r < 4; r++) acc[i][j][r] = 0.f;

    int nT = K / BK;

    tcga_issue(sb0,          A, B, m0, Mend, n0, N, K, 0,  tid); cpa_commit();
    tcga_issue(sb0 + STAGEB, A, B, m0, Mend, n0, N, K, BK, tid); cpa_commit();

    int buf = 0;
    for (int t = 0; t < nT; t++) {
        cpa_wait1();
        __syncthreads();
        if (t + 2 < nT) {
            int nb = buf + 2; if (nb >= 3) nb -= 3;
            tcga_issue(sb0 + nb*STAGEB, A, B, m0, Mend, n0, N, K, (t + 2)*BK, tid);
        }
        cpa_commit();

        const float* sA = smtc + (size_t)buf * (STAGEB/4);
        const float* sB = sA + 4096;
#pragma unroll
        for (int g = 0; g < 2; g++) {
            int ch = ((g*4 + tig) ^ swl) << 2;
            float4 bq[4];
#pragma unroll
            for (int j = 0; j < 4; j++)
                bq[j] = *(const float4*)&sB[(wn + j*8 + grp)*32 + ch];
#pragma unroll
            for (int i = 0; i < 4; i++) {
                int ra = (wm + i*16 + grp)*32 + ch;
                float4 alo = *(const float4*)&sA[ra];
                float4 ahi = *(const float4*)&sA[ra + 8*32];
#pragma unroll
                for (int j = 0; j < 4; j++) {
                    mma_tf32(acc[i][j], make_float2(alo.x, alo.y),
                             make_float2(ahi.x, ahi.y), make_float2(bq[j].x, bq[j].y));
                    mma_tf32(acc[i][j], make_float2(alo.z, alo.w),
                             make_float2(ahi.z, ahi.w), make_float2(bq[j].z, bq[j].w));
                }
            }
        }
        buf = (buf == 2) ? 0 : buf + 1;
    }

#pragma unroll
    for (int i = 0; i < 4; i++) {
#pragma unroll
        for (int j = 0; j < 4; j++) {
#pragma unroll
            for (int half = 0; half < 2; half++) {
                int row = m0 + wm + i*16 + grp + half*8;
                int col = n0 + wn + j*8 + tig*2;
                if (row >= Mend || col >= N) continue;
                float a0 = acc[i][j][2*half+0]*TRUNC_COMP;
                float a1 = acc[i][j][2*half+1]*TRUNC_COMP;
                if (EPI == 0) {
                    float2 v = make_float2(a0, a1);
                    if (R) { v.x += R[(size_t)row*N + col]; v.y += R[(size_t)row*N + col+1]; }
                    *(float2*)(C + (size_t)row*N + col) = v;
                    if (C2) *(float2*)(C2 + (size_t)row*N + col) = v;
                } else {
                    int tok = g_rows[row];
                    float w = g_roww[row];
                    atomicAdd(C + (size_t)tok*N + col,     w*a0);
                    atomicAdd(C + (size_t)tok*N + col + 1, w*a1);
                }
            }
        }
    }
}

__global__ __launch_bounds__(256, 2) void gemm_tf32_kernel(
    const float* __restrict__ A, const float* __restrict__ B,
    float* __restrict__ C, const float* __restrict__ R, float* __restrict__ C2,
    int M, int N, int K) {
    gemm_tf32_body<0>(A, B, C, R, C2, blockIdx.y*BM, M, blockIdx.x*BN, N, K);
}

__global__ __launch_bounds__(256, 2) void gemm_qkv_kernel(
    const float* __restrict__ A,
    const float* __restrict__ wq, const float* __restrict__ wk, const float* __restrict__ wv) {
    int nb = blockIdx.x;
    const float* B; float* C; int n0, N;
    if (nb < 16)      { B = wq; C = g_q; n0 = nb*BN;       N = NHEAD*HD; }
    else if (nb < 20) { B = wk; C = g_k; n0 = (nb-16)*BN;  N = NKVH*HD;  }
    else              { B = wv; C = g_v; n0 = (nb-20)*BN;  N = NKVH*HD;  }
    gemm_tf32_body<0>(A, B, C, nullptr, nullptr, blockIdx.y*BM, SQ, n0, N, HDIM);
}

// w2 grouped GEMM, epilogue scatters weighted rows into `out` via atomicAdd
__global__ __launch_bounds__(256, 2) void gemm_w2out_group_kernel(
    const float* __restrict__ A, const float* __restrict__ Ball,
    float* __restrict__ out, int N, int K) {
    int e = blockIdx.z;
    int mstart = g_off[e], mend = g_off[e+1];
    int m0 = mstart + blockIdx.y*BM;
    if (m0 >= mend) return;
    gemm_tf32_body<2>(A, Ball + (size_t)e*N*K, out, nullptr, nullptr,
                      m0, mend, blockIdx.x*BN, N, K);
}

// ---------------- Fused w1+w3 grouped GEMM with silu epilogue ----------------
__device__ __forceinline__ void w13_issue(
    unsigned sbase, const float* __restrict__ A,
    const float* __restrict__ B1, const float* __restrict__ B3,
    int m0, int Mend, int n0, int K, int ks, int tid)
{
#pragma unroll
    for (int i = 0; i < 8; i++) {
        int idx = tid + i*256;
        int isB = idx >> 10;
        int l = idx & 1023;
        int r = l >> 3, c = l & 7;
        const float* src;
        int bytes = 16;
        if (!isB) {
            src = A + (size_t)(m0 + r)*K + ks + (c << 2);
            if (m0 + r >= Mend) bytes = 0;
        } else {
            const float* Bsel = (r < 64) ? B1 : B3;
            src = Bsel + (size_t)(n0 + (r & 63))*K + ks + (c << 2);
        }
        int csw = c ^ ((r & 1) << 2);
        unsigned dst = sbase + (isB ? 16384u : 0u) + (unsigned)(r*128 + csw*16);
        cpa16(dst, src, bytes);
    }
}

__global__ __launch_bounds__(256, 2) void gemm_w13silu_group_kernel(
    const float* __restrict__ A, const float* __restrict__ W1all,
    const float* __restrict__ W3all, float* __restrict__ b1out) {
    int e = blockIdx.z;
    int mstart = g_off[e], mend = g_off[e+1];
    int m0 = mstart + blockIdx.y*BM;
    if (m0 >= mend) return;
    int n0 = blockIdx.x * 64;
    const float* B1 = W1all + (size_t)e*IDIM*HDIM;
    const float* B3 = W3all + (size_t)e*IDIM*HDIM;
    const int K = HDIM;

    extern __shared__ float smtc[];
    unsigned sb0 = smem_u32(smtc);
    int tid = threadIdx.x;
    int lane = tid & 31, wid = tid >> 5;
    int wm = (wid & 1) * 64;
    int wn = (wid >> 1) * 16;
    int tig = lane & 3, grp = lane >> 2;
    int swl = (grp & 1) << 2;

    float acc1[4][2][4], acc3[4][2][4];
#pragma unroll
    for (int i = 0; i < 4; i++)
#pragma unroll
        for (int j = 0; j < 2; j++)
#pragma unroll
            for (int r = 0; r < 4; r++) { acc1[i][j][r] = 0.f; acc3[i][j][r] = 0.f; }

    int nT = K / BK;
    w13_issue(sb0,          A, B1, B3, m0, mend, n0, K, 0,  tid); cpa_commit();
    w13_issue(sb0 + STAGEB, A, B1, B3, m0, mend, n0, K, BK, tid); cpa_commit();

    int buf = 0;
    for (int t = 0; t < nT; t++) {
        cpa_wait1();
        __syncthreads();
        if (t + 2 < nT) {
            int nb = buf + 2; if (nb >= 3) nb -= 3;
            w13_issue(sb0 + nb*STAGEB, A, B1, B3, m0, mend, n0, K, (t + 2)*BK, tid);
        }
        cpa_commit();

        const float* sA = smtc + (size_t)buf * (STAGEB/4);
        const float* sB = sA + 4096;
#pragma unroll
        for (int g = 0; g < 2; g++) {
            int ch = ((g*4 + tig) ^ swl) << 2;
            float4 b1q[2], b3q[2];
#pragma unroll
            for (int j = 0; j < 2; j++) {
                b1q[j] = *(const float4*)&sB[(wn + j*8 + grp)*32 + ch];
                b3q[j] = *(const float4*)&sB[(64 + wn + j*8 + grp)*32 + ch];
            }
#pragma unroll
            for (int i = 0; i < 4; i++) {
                int ra = (wm + i*16 + grp)*32 + ch;
                float4 alo = *(const float4*)&sA[ra];
                float4 ahi = *(const float4*)&sA[ra + 8*32];
#pragma unroll
                for (int j = 0; j < 2; j++) {
                    mma_tf32(acc1[i][j], make_float2(alo.x, alo.y),
                             make_float2(ahi.x, ahi.y), make_float2(b1q[j].x, b1q[j].y));
                    mma_tf32(acc1[i][j], make_float2(alo.z, alo.w),
                             make_float2(ahi.z, ahi.w), make_float2(b1q[j].z, b1q[j].w));
                    mma_tf32(acc3[i][j], make_float2(alo.x, alo.y),
                             make_float2(ahi.x, ahi.y), make_float2(b3q[j].x, b3q[j].y));
                    mma_tf32(acc3[i][j], make_float2(alo.z, alo.w),
                             make_float2(ahi.z, ahi.w), make_float2(b3q[j].z, b3q[j].w));
                }
            }
        }
        buf = (buf == 2) ? 0 : buf + 1;
    }

#pragma unroll
    for (int i = 0; i < 4; i++) {
#pragma unroll
        for (int j = 0; j < 2; j++) {
#pragma unroll
            for (int half = 0; half < 2; half++) {
                int row = m0 + wm + i*16 + grp + half*8;
                if (row >= mend) continue;
                int col = n0 + wn + j*8 + tig*2;
                float v1a = acc1[i][j][2*half+0]*TRUNC_COMP;
                float v1b = acc1[i][j][2*half+1]*TRUNC_COMP;
                float v3a = acc3[i][j][2*half+0]*TRUNC_COMP;
                float v3b = acc3[i][j][2*half+1]*TRUNC_COMP;
                float ga = v1a / (1.f + __expf(-v1a));
                float gb = v1b / (1.f + __expf(-v1b));
                float2 v = make_float2(f2tf32rn(ga*v3a), f2tf32rn(gb*v3b));
                *(float2*)(b1out + (size_t)row*IDIM + col) = v;
            }
        }
    }
}

// ------------------------- RoPE (in-place, outputs tf32-rounded) -------------------------
__global__ void rope_kernel(float* __restrict__ q, float* __restrict__ k) {
    int s  = blockIdx.x;
    int hh = blockIdx.y;
    int d2 = threadIdx.x;
    float* p;
    if (hh < NHEAD) p = q + (size_t)s*(NHEAD*HD) + hh*HD;
    else            p = k + (size_t)s*(NKVH*HD) + (hh-NHEAD)*HD;
    float ps = g_posf[s];
    float inv = exp2f(-(float)d2 * 0.41524101186092029f);
    float ang = ps * inv;
    float sn, cs;
    sincosf(ang, &sn, &cs);
    float x1 = p[d2], x2 = p[d2+32];
    p[d2]    = f2tf32rn(x1*cs - x2*sn);
    p[d2+32] = f2tf32rn(x2*cs + x1*sn);
}

// ------------------------- Flash attention on tf32 mma.sync -------------------------
#define AQT 128
#define AKT 32

__global__ __launch_bounds__(256) void attn_mma_kernel(
    const float* __restrict__ q, const float* __restrict__ k,
    const float* __restrict__ v, float* __restrict__ ctx)
{
    __shared__ float sm[8192];
    int bq = gridDim.x - 1 - blockIdx.x;   // heavy tiles first
    int h = blockIdx.y;
    int kvh = h >> 2;
    int q0 = bq * AQT;
    int tid = threadIdx.x, wid = tid >> 5, lane = tid & 31;
    int tig = lane & 3, grp = lane >> 2;

#pragma unroll
    for (int i = 0; i < 8; i++) {
        int fid = tid + i*256;
        int row = fid >> 4, c4 = fid & 15;
        float4 vq = *(const float4*)(q + (size_t)(q0+row)*(NHEAD*HD) + h*HD + (c4 << 2));
        int g = c4 >> 2, sw = (row & 3) ^ ((row >> 2) & 1);
        float* d = &sm[row*64 + g*16 + (c4 & 3)];
        d[((0^sw)<<2)] = vq.x; d[((1^sw)<<2)] = vq.y;
        d[((2^sw)<<2)] = vq.z; d[((3^sw)<<2)] = vq.w;
    }
    __syncthreads();
    int r0 = wid*16 + grp;
    int swA = (grp & 3) ^ ((grp >> 2) & 1);
    int chA = ((tig ^ swA) << 2);
    float4 qf0[4], qf1[4];
#pragma unroll
    for (int g = 0; g < 4; g++) {
        qf0[g] = *(const float4*)&sm[r0*64 + g*16 + chA];
        qf1[g] = *(const float4*)&sm[(r0+8)*64 + g*16 + chA];
    }
    __syncthreads();

    int qrow0 = q0 + r0, qrow1 = qrow0 + 8;
    float m0 = -INFINITY, m1 = -INFINITY, l0 = 0.f, l1 = 0.f;
    float oa[8][4];
#pragma unroll
    for (int j = 0; j < 8; j++)
#pragma unroll
        for (int r = 0; r < 4; r++) oa[j][r] = 0.f;

    float* pslab = &sm[4096 + wid*512];
    int chP = chA;

    int nkt = 4*bq + 4;
    for (int kt = 0; kt < nkt; kt++) {
#pragma unroll
        for (int i = 0; i < 2; i++) {
            int fid = tid + i*256;
            int row = fid >> 4, c4 = fid & 15;
            size_t goff = (size_t)(kt*AKT + row)*(NKVH*HD) + kvh*HD + (c4 << 2);
            float4 kv4 = *(const float4*)(k + goff);
            int g = c4 >> 2, sw = (row & 3) ^ ((row >> 2) & 1);
            float* d = &sm[row*64 + g*16 + (c4 & 3)];
            d[((0^sw)<<2)] = kv4.x; d[((1^sw)<<2)] = kv4.y;
            d[((2^sw)<<2)] = kv4.z; d[((3^sw)<<2)] = kv4.w;
            float4 vv4 = *(const float4*)(v + goff);
            float vals[4] = {vv4.x, vv4.y, vv4.z, vv4.w};
            int k16 = row & 15;
            int cbase = (row >> 4)*16 + (k16 >> 2);
#pragma unroll
            for (int e = 0; e < 4; e++) {
                int dp = (c4 << 2) + e;
                int sw2 = (dp & 3) ^ ((dp >> 2) & 1);
                sm[2048 + dp*32 + cbase + (((k16 & 3) ^ sw2) << 2)] = f2tf32rn(vals[e]);
            }
        }
        __syncthreads();

        float sc[4][4];
#pragma unroll
        for (int j = 0; j < 4; j++)
#pragma unroll
            for (int r = 0; r < 4; r++) sc[j][r] = 0.f;
#pragma unroll
        for (int j = 0; j < 4; j++) {
            int krow = j*8 + grp;
            int swB = (krow & 3) ^ ((krow >> 2) & 1);
            int chB = ((tig ^ swB) << 2);
#pragma unroll
            for (int g = 0; g < 4; g++) {
                float4 bf = *(const float4*)&sm[krow*64 + g*16 + chB];
                mma_tf32(sc[j], make_float2(qf0[g].x, qf0[g].y),
                         make_float2(qf1[g].x, qf1[g].y), make_float2(bf.x, bf.y));
                mma_tf32(sc[j], make_float2(qf0[g].z, qf0[g].w),
                         make_float2(qf1[g].z, qf1[g].w), make_float2(bf.z, bf.w));
            }
        }

        float lm0 = -INFINITY, lm1 = -INFINITY;
#pragma unroll
        for (int j = 0; j < 4; j++) {
            int col = kt*AKT + j*8 + 2*tig;
            sc[j][0] = (col     <= qrow0) ? sc[j][0]*0.125f : -1e30f;
            sc[j][1] = (col + 1 <= qrow0) ? sc[j][1]*0.125f : -1e30f;
            sc[j][2] = (col     <= qrow1) ? sc[j][2]*0.125f : -1e30f;
            sc[j][3] = (col + 1 <= qrow1) ? sc[j][3]*0.125f : -1e30f;
            lm0 = fmaxf(lm0, fmaxf(sc[j][0], sc[j][1]));
            lm1 = fmaxf(lm1, fmaxf(sc[j][2], sc[j][3]));
        }
        lm0 = fmaxf(lm0, __shfl_xor_sync(0xffffffffu, lm0, 1));
        lm0 = fmaxf(lm0, __shfl_xor_sync(0xffffffffu, lm0, 2));
        lm1 = fmaxf(lm1, __shfl_xor_sync(0xffffffffu, lm1, 1));
        lm1 = fmaxf(lm1, __shfl_xor_sync(0xffffffffu, lm1, 2));
        float mn0 = fmaxf(m0, lm0), mn1 = fmaxf(m1, lm1);
        float s0 = __expf(m0 - mn0), s1 = __expf(m1 - mn1);
        float ps0 = 0.f, ps1 = 0.f;
#pragma unroll
        for (int j = 0; j < 4; j++) {
            sc[j][0] = __expf(sc[j][0] - mn0);
            sc[j][1] = __expf(sc[j][1] - mn0);
            sc[j][2] = __expf(sc[j][2] - mn1);
            sc[j][3] = __expf(sc[j][3] - mn1);
            ps0 += sc[j][0] + sc[j][1];
            ps1 += sc[j][2] + sc[j][3];
        }
        ps0 += __shfl_xor_sync(0xffffffffu, ps0, 1);
        ps0 += __shfl_xor_sync(0xffffffffu, ps0, 2);
        ps1 += __shfl_xor_sync(0xffffffffu, ps1, 1);
        ps1 += __shfl_xor_sync(0xffffffffu, ps1, 2);
        l0 = l0*s0 + ps0; l1 = l1*s1 + ps1;
        m0 = mn0; m1 = mn1;
#pragma unroll
        for (int j = 0; j < 8; j++) {
            oa[j][0] *= s0; oa[j][1] *= s0;
            oa[j][2] *= s1; oa[j][3] *= s1;
        }

#pragma unroll
        for (int j = 0; j < 4; j++) {
            int g2 = j >> 1;
            int k16a = (j & 1)*8 + 2*tig;
            int k16b = k16a + 1;
            int c0 = g2*16 + (((k16a & 3) ^ swA) << 2) + (k16a >> 2);
            int c1 = g2*16 + (((k16b & 3) ^ swA) << 2) + (k16b >> 2);
            pslab[grp*32 + c0]     = f2tf32rn(sc[j][0]);
            pslab[grp*32 + c1]     = f2tf32rn(sc[j][1]);
            pslab[(grp+8)*32 + c0] = f2tf32rn(sc[j][2]);
            pslab[(grp+8)*32 + c1] = f2tf32rn(sc[j][3]);
        }
        __syncwarp();
        float4 pf0[2], pf1[2];
#pragma unroll
        for (int g = 0; g < 2; g++) {
            pf0[g] = *(const float4*)&pslab[grp*32 + g*16 + chP];
            pf1[g] = *(const float4*)&pslab[(grp+8)*32 + g*16 + chP];
        }

#pragma unroll
        for (int jd = 0; jd < 8; jd++) {
            int vrow = jd*8 + grp;
            int swV = (vrow & 3) ^ ((vrow >> 2) & 1);
            int chV = ((tig ^ swV) << 2);
#pragma unroll
            for (int g = 0; g < 2; g++) {
                float4 bf = *(const float4*)&sm[2048 + vrow*32 + g*16 + chV];
                mma_tf32(oa[jd], make_float2(pf0[g].x, pf0[g].y),
                         make_float2(pf1[g].x, pf1[g].y), make_float2(bf.x, bf.y));
                mma_tf32(oa[jd], make_float2(pf0[g].z, pf0[g].w),
                         make_float2(pf1[g].z, pf1[g].w), make_float2(bf.z, bf.w));
            }
        }
        __syncthreads();
    }

    float rl0 = 1.f / l0, rl1 = 1.f / l1;
#pragma unroll
    for (int jd = 0; jd < 8; jd++) {
        int dcol = jd*8 + 2*tig;
        float2 v0 = make_float2(f2tf32rn(oa[jd][0]*rl0), f2tf32rn(oa[jd][1]*rl0));
        float2 v1 = make_float2(f2tf32rn(oa[jd][2]*rl1), f2tf32rn(oa[jd][3]*rl1));
        *(float2*)(ctx + (size_t)qrow0*(NHEAD*HD) + h*HD + dcol) = v0;
        *(float2*)(ctx + (size_t)qrow1*(NHEAD*HD) + h*HD + dcol) = v1;
    }
}

// ------------------------- MoE routing -------------------------
__global__ void router_kernel(const float* __restrict__ x, const float* __restrict__ wg) {
    int t = blockIdx.x;
    int warp = threadIdx.x >> 5, lane = threadIdx.x & 31;
    const float* xr = x + (size_t)t*HDIM;
    const float* wr = wg + (size_t)warp*HDIM;
    float s = 0.f;
    for (int c = lane; c < HDIM; c += 32) s += xr[c]*wr[c];
    for (int off = 16; off; off >>= 1) s += __shfl_xor_sync(0xffffffffu, s, off);
    __shared__ float lg[NE];
    if (lane == 0) lg[warp] = s;
    __syncthreads();
    if (threadIdx.x == 0) {
        int i0 = 0;
        for (int e = 1; e < NE; e++) if (lg[e] > lg[i0]) i0 = e;
        int i1 = (i0 == 0) ? 1 : 0;
        for (int e = 0; e < NE; e++) { if (e == i0) continue; if (lg[e] > lg[i1]) i1 = e; }
        float w0 = 1.f / (1.f + __expf(lg[i1] - lg[i0]));
        for (int e = 0; e < NE; e++) g_rlog[t*NE + e] = lg[e];
        g_tok2e[t*2]   = i0; g_tok2e[t*2+1] = i1;
        g_tok2w[t*2]   = w0; g_tok2w[t*2+1] = 1.f - w0;
        atomicAdd(&g_cnt[i0], 1);
        atomicAdd(&g_cnt[i1], 1);
    }
}

__global__ void scan_kernel() {
    if (threadIdx.x == 0) {
        int acc = 0;
        for (int e = 0; e < NE; e++) { g_off[e] = acc; acc += g_cnt[e]; }
        g_off[NE] = acc;
    }
}

__global__ void scatter_kernel() {
    int t = blockIdx.x*blockDim.x + threadIdx.x;
    if (t >= SQ) return;
#pragma unroll
    for (int sl = 0; sl < 2; sl++) {
        int e = g_tok2e[t*2+sl];
        int rrel = atomicAdd(&g_cur[e], 1);
        int rr = g_off[e] + rrel;
        g_rows[rr] = t;
        g_roww[rr] = g_tok2w[t*2+sl];
    }
}

__global__ void gather_kernel() {
    int total = SQ*2*(HDIM/4);
    for (int idx = blockIdx.x*blockDim.x + threadIdx.x; idx < total; idx += gridDim.x*blockDim.x) {
        int row = idx / (HDIM/4);
        int c4  = idx % (HDIM/4);
        float4 v = ((const float4*)g_xn2)[(size_t)g_rows[row]*(HDIM/4) + c4];
        v.x = f2tf32rn(v.x); v.y = f2tf32rn(v.y);
        v.z = f2tf32rn(v.z); v.w = f2tf32rn(v.w);
        ((float4*)g_xg)[(size_t)row*(HDIM/4) + c4] = v;
    }
}

// ------------------------- output tail writers -------------------------
__global__ void gate_kernel(float* __restrict__ dst, const float* __restrict__ gin) {
    int i = blockIdx.x*blockDim.x + threadIdx.x;
    int total = 4*SQ*NE;
    if (i < total) dst[i] = (i < SQ*NE) ? g_rlog[i] : gin[i];
}

__global__ void posf_kernel(float* __restrict__ dst, int n) {
    int i = blockIdx.x*blockDim.x + threadIdx.x;
    if (i < n) dst[i] = g_posf[i];
}

__global__ void posraw_kernel(float* __restrict__ dst, int n) {
    int i = blockIdx.x*blockDim.x + threadIdx.x;
    if (i < n) ((long long*)dst)[i] = (long long)g_posf[i];
}

__global__ void zerofill_kernel(float* __restrict__ dst, int n) {
    int i = blockIdx.x*blockDim.x + threadIdx.x;
    if (i < n) dst[i] = 0.f;
}

// ------------------------- launch -------------------------
extern "C" void kernel_launch(void* const* d_in, const int* in_sizes, int n_in,
                              void* d_out, int out_size) {
    const float* hidden = (const float*)d_in[0];
    const void*  posraw = d_in[1];
    const float* gatein = (const float*)d_in[2];
    const float* ln1 = (const float*)d_in[3];
    const float* ln2 = (const float*)d_in[4];
    const float* wq  = (const float*)d_in[5];
    const float* wk  = (const float*)d_in[6];
    const float* wv  = (const float*)d_in[7];
    const float* wo  = (const float*)d_in[8];
    const float* wg  = (const float*)d_in[9];
    const float* w1  = (const float*)d_in[10];
    const float* w2  = (const float*)d_in[11];
    const float* w3  = (const float*)d_in[12];

    float *xn1,*q,*k,*v,*ctx,*resid1,*xn2,*xg,*b1;
    cudaGetSymbolAddress((void**)&xn1,    g_xn1);
    cudaGetSymbolAddress((void**)&q,      g_q);
    cudaGetSymbolAddress((void**)&k,      g_k);
    cudaGetSymbolAddress((void**)&v,      g_v);
    cudaGetSymbolAddress((void**)&ctx,    g_ctx);
    cudaGetSymbolAddress((void**)&resid1, g_resid1);
    cudaGetSymbolAddress((void**)&xn2,    g_xn2);
    cudaGetSymbolAddress((void**)&xg,     g_xg);
    cudaGetSymbolAddress((void**)&b1,     g_b1);

    cudaFuncSetAttribute(gemm_tf32_kernel,          cudaFuncAttributeMaxDynamicSharedMemorySize, SMEMTC);
    cudaFuncSetAttribute(gemm_qkv_kernel,           cudaFuncAttributeMaxDynamicSharedMemorySize, SMEMTC);
    cudaFuncSetAttribute(gemm_w2out_group_kernel,   cudaFuncAttributeMaxDynamicSharedMemorySize, SMEMTC);
    cudaFuncSetAttribute(gemm_w13silu_group_kernel, cudaFuncAttributeMaxDynamicSharedMemorySize, SMEMTC);

    float* out = (float*)d_out;
    const int HTOT = SQ*HDIM;
    const int GTOT = 4*SQ*NE;

    posdetect_kernel<<<1, 256>>>((const unsigned int*)posraw);
    posconv_kernel<<<SQ/256, 256>>>(posraw);

    // attention path
    rmsnorm_kernel<<<SQ, 256>>>(hidden, ln1, xn1, 1);
    gemm_qkv_kernel<<<dim3(24, SQ/BM), 256, SMEMTC>>>(xn1, wq, wk, wv);
    rope_kernel<<<dim3(SQ, NHEAD+NKVH), 32>>>(q, k);
    attn_mma_kernel<<<dim3(SQ/AQT, NHEAD), 256>>>(q, k, v, ctx);
    dim3 gq(HDIM/BN, SQ/BM);
    // o-proj: writes resid1 AND the h-region of out (residual base for MoE adds)
    gemm_tf32_kernel<<<gq, 256, SMEMTC>>>(ctx, wo, resid1, hidden, out, SQ, HDIM, HDIM);

    // MoE path
    rmsnorm_kernel<<<SQ, 256>>>(resid1, ln2, xn2, 0);
    router_kernel<<<SQ, 256>>>(xn2, wg);
    scan_kernel<<<1, 32>>>();
    scatter_kernel<<<SQ/256, 256>>>();
    gather_kernel<<<512, 256>>>();
    gemm_w13silu_group_kernel<<<dim3(IDIM/64, SQ/BM, NE), 256, SMEMTC>>>(xg, w1, w3, b1);
    gemm_w2out_group_kernel<<<dim3(HDIM/BN, SQ/BM, NE), 256, SMEMTC>>>(b1, w2, out, HDIM, IDIM);

    int rem = out_size - HTOT;
    if (rem >= GTOT) {
        gate_kernel<<<(GTOT+255)/256, 256>>>(out + (out_size - GTOT), gatein);
        rem -= GTOT;
    }
    if (rem == SQ) {
        posf_kernel<<<(SQ+255)/256, 256>>>(out + HTOT, SQ);
    } else if (rem == 2*SQ) {
        posraw_kernel<<<(SQ+255)/256, 256>>>(out + HTOT, SQ);
    } else if (rem > 0) {
        zerofill_kernel<<<(rem+255)/256, 256>>>(out + HTOT, rem);
    }
}

// round 17
// speedup vs baseline: 1.0090x; 1.0090x over previous
#include <cuda_runtime.h>
#include <math.h>

#define HDIM 2048
#define SQ   2048
#define NHEAD 32
#define NKVH  8
#define HD    64
#define IDIM  4096
#define NE    8

// ------------------------- scratch (static, no allocs) -------------------------
__device__ float g_xn1[SQ*HDIM];
__device__ float g_q[SQ*NHEAD*HD];
__device__ float g_k[SQ*NKVH*HD];
__device__ float g_v[SQ*NKVH*HD];
__device__ float g_ctx[SQ*NHEAD*HD];
__device__ float g_resid1[SQ*HDIM];
__device__ float g_xn2[SQ*HDIM];
__device__ float g_rlog[SQ*NE];
__device__ int   g_tok2e[SQ*2];
__device__ float g_tok2w[SQ*2];
__device__ int   g_tok2row[SQ*2];
__device__ int   g_rows[SQ*2];
__device__ int   g_cnt[NE];
__device__ int   g_off[NE+1];
__device__ int   g_cur[NE];
__device__ float g_xg[SQ*2*HDIM];
__device__ float g_b1[SQ*2*IDIM];
__device__ float g_y[SQ*2*HDIM];
__device__ int   g_pos64;
__device__ float g_posf[SQ];

// tf32 round-to-nearest
__device__ __forceinline__ float f2tf32rn(float f) {
    unsigned r;
    asm("cvt.rna.tf32.f32 %0, %1;" : "=r"(r) : "f"(f));
    return __uint_as_float(r);
}

// B-operand arrives raw via cp.async -> HW tf32-truncates (multiplicative mean
// shrink ~3.52e-4). Compensate the accumulator once in the epilogue.
#define TRUNC_COMP 1.000352f

// ------------------------- position width detection (+ MoE counter reset) ----
__global__ void posdetect_kernel(const unsigned int* __restrict__ p) {
    __shared__ int ok;
    if (threadIdx.x == 0) ok = 1;
    __syncthreads();
    int bad = 0;
    for (int i = threadIdx.x; i < SQ/2; i += blockDim.x)
        if (p[2*i+1] != 0u) bad = 1;
    if (bad) atomicAnd(&ok, 0);
    __syncthreads();
    if (threadIdx.x == 0) g_pos64 = ok;
    if (threadIdx.x < NE) { g_cnt[threadIdx.x] = 0; g_cur[threadIdx.x] = 0; }
}

__global__ void posconv_kernel(const void* __restrict__ p) {
    int i = blockIdx.x*blockDim.x + threadIdx.x;
    if (i >= SQ) return;
    long long v = g_pos64 ? ((const long long*)p)[i]
                          : (long long)((const int*)p)[i];
    g_posf[i] = (float)v;
}

// ------------------------- RMSNorm (attention path, tf32-rounded out) -------------------------
__global__ void rmsnorm_kernel(const float* __restrict__ x, const float* __restrict__ w,
                               float* __restrict__ o) {
    int row = blockIdx.x;
    const float* xr = x + (size_t)row*HDIM;
    float s = 0.f;
    for (int c = threadIdx.x; c < HDIM; c += blockDim.x) { float v = xr[c]; s += v*v; }
    __shared__ float red[8];
    for (int off = 16; off; off >>= 1) s += __shfl_xor_sync(0xffffffffu, s, off);
    int warp = threadIdx.x >> 5, lane = threadIdx.x & 31;
    if (lane == 0) red[warp] = s;
    __syncthreads();
    if (warp == 0) {
        float t = (lane < 8) ? red[lane] : 0.f;
        for (int off = 4; off; off >>= 1) t += __shfl_xor_sync(0xffffffffu, t, off);
        if (lane == 0) red[0] = t;
    }
    __syncthreads();
    float inv = rsqrtf(red[0] / (float)HDIM + 1e-5f);
    float* orow = o + (size_t)row*HDIM;
    for (int c = threadIdx.x; c < HDIM; c += blockDim.x)
        orow[c] = f2tf32rn(xr[c] * inv * w[c]);
}

// ---------------- Fused RMSNorm-2 + MoE router (one block per token) ----------------
// Writes raw-fp32 xn2 (gather rounds later) and computes all 8 expert logits
// from the smem copy (8 warps = 8 experts; summation order identical to the
// old standalone router, so routing is bit-identical).
__global__ void rmsnorm_router_kernel(const float* __restrict__ x, const float* __restrict__ w,
                                      float* __restrict__ o, const float* __restrict__ wg) {
    __shared__ float xs[HDIM];
    __shared__ float red[8];
    __shared__ float lg[NE];
    int row = blockIdx.x;
    const float* xr = x + (size_t)row*HDIM;
    float s = 0.f;
    for (int c = threadIdx.x; c < HDIM; c += blockDim.x) {
        float v = xr[c]; xs[c] = v; s += v*v;
    }
    for (int off = 16; off; off >>= 1) s += __shfl_xor_sync(0xffffffffu, s, off);
    int warp = threadIdx.x >> 5, lane = threadIdx.x & 31;
    if (lane == 0) red[warp] = s;
    __syncthreads();
    if (warp == 0) {
        float t = (lane < 8) ? red[lane] : 0.f;
        for (int off = 4; off; off >>= 1) t += __shfl_xor_sync(0xffffffffu, t, off);
        if (lane == 0) red[0] = t;
    }
    __syncthreads();
    float inv = rsqrtf(red[0] / (float)HDIM + 1e-5f);
    float* orow = o + (size_t)row*HDIM;
    for (int c = threadIdx.x; c < HDIM; c += blockDim.x) {
        float nv = xs[c] * inv * w[c];
        xs[c] = nv;
        orow[c] = nv;
    }
    __syncthreads();
    // router: warp e computes logit e
    const float* wr = wg + (size_t)warp*HDIM;
    float t = 0.f;
    for (int c = lane; c < HDIM; c += 32) t += xs[c]*wr[c];
    for (int off = 16; off; off >>= 1) t += __shfl_xor_sync(0xffffffffu, t, off);
    if (lane == 0) lg[warp] = t;
    __syncthreads();
    if (threadIdx.x == 0) {
        int i0 = 0;
        for (int e = 1; e < NE; e++) if (lg[e] > lg[i0]) i0 = e;
        int i1 = (i0 == 0) ? 1 : 0;
        for (int e = 0; e < NE; e++) { if (e == i0) continue; if (lg[e] > lg[i1]) i1 = e; }
        float w0 = 1.f / (1.f + __expf(lg[i1] - lg[i0]));
        for (int e = 0; e < NE; e++) g_rlog[row*NE + e] = lg[e];
        g_tok2e[row*2]   = i0; g_tok2e[row*2+1] = i1;
        g_tok2w[row*2]   = w0; g_tok2w[row*2+1] = 1.f - w0;
        atomicAdd(&g_cnt[i0], 1);
        atomicAdd(&g_cnt[i1], 1);
    }
}

// ------------------------- TF32 HMMA GEMM (NT), cp.async BK32, 3-stage -------------------------
#define BM 128
#define BN 128
#define BK 32
#define STAGEB 32768           // bytes per stage (A 16KB + B 16KB)
#define NSTAGE 3
#define SMEMTC (NSTAGE*STAGEB)

__device__ __forceinline__ void mma_tf32(float c[4], float2 alo, float2 ahi, float2 b) {
    asm volatile(
        "mma.sync.aligned.m16n8k8.row.col.f32.tf32.tf32.f32 "
        "{%0,%1,%2,%3}, {%4,%5,%6,%7}, {%8,%9}, {%0,%1,%2,%3};\n"
        : "+f"(c[0]), "+f"(c[1]), "+f"(c[2]), "+f"(c[3])
        : "r"(__float_as_uint(alo.x)), "r"(__float_as_uint(ahi.x)),
          "r"(__float_as_uint(alo.y)), "r"(__float_as_uint(ahi.y)),
          "r"(__float_as_uint(b.x)),   "r"(__float_as_uint(b.y)));
}

__device__ __forceinline__ unsigned smem_u32(const void* p) {
    unsigned a;
    asm("{ .reg .u64 t; cvta.to.shared.u64 t, %1; cvt.u32.u64 %0, t; }" : "=r"(a) : "l"(p));
    return a;
}

__device__ __forceinline__ void cpa16(unsigned dst, const float* src, int bytes) {
    asm volatile("cp.async.cg.shared.global [%0], [%1], 16, %2;"
                 :: "r"(dst), "l"(src), "r"(bytes) : "memory");
}
__device__ __forceinline__ void cpa_commit() {
    asm volatile("cp.async.commit_group;" ::: "memory");
}
__device__ __forceinline__ void cpa_wait1() {
    asm volatile("cp.async.wait_group 1;" ::: "memory");
}

// one BK32 stage: 128 rows x 8 chunks x 2 operands = 2048 chunks, 8/thread
__device__ __forceinline__ void tcga_issue(
    unsigned sbase, const float* __restrict__ A, const float* __restrict__ B,
    int m0, int Mend, int n0, int N, int K, int ks, int tid)
{
#pragma unroll
    for (int i = 0; i < 8; i++) {
        int idx = tid + i*256;
        int isB = idx >> 10;
        int l = idx & 1023;
        int r = l >> 3, c = l & 7;
        const float* src;
        int bytes;
        if (!isB) { src = A + (size_t)(m0 + r)*K + ks + (c << 2); bytes = (m0 + r < Mend) ? 16 : 0; }
        else      { src = B + (size_t)(n0 + r)*K + ks + (c << 2); bytes = (n0 + r < N)    ? 16 : 0; }
        int csw = c ^ ((r & 1) << 2);
        unsigned dst = sbase + (isB ? 16384u : 0u) + (unsigned)(r*128 + csw*16);
        cpa16(dst, src, bytes);
    }
}

__device__ __forceinline__ void gemm_tf32_body(
    const float* __restrict__ A, const float* __restrict__ B,
    float* __restrict__ C, const float* __restrict__ R,
    int m0, int Mend, int n0, int N, int K)
{
    extern __shared__ float smtc[];
    unsigned sb0 = smem_u32(smtc);
    int tid = threadIdx.x;
    int lane = tid & 31, wid = tid >> 5;
    int wm = (wid & 1) * 64;
    int wn = (wid >> 1) * 32;
    int tig = lane & 3, grp = lane >> 2;
    int swl = (grp & 1) << 2;

    float acc[4][4][4];
#pragma unroll
    for (int i = 0; i < 4; i++)
#pragma unroll
        for (int j = 0; j < 4; j++)
#pragma unroll
            for (int r = 0; r < 4; r++) acc[i][j][r] = 0.f;

    int nT = K / BK;

    tcga_issue(sb0,          A, B, m0, Mend, n0, N, K, 0,  tid); cpa_commit();
    tcga_issue(sb0 + STAGEB, A, B, m0, Mend, n0, N, K, BK, tid); cpa_commit();

    int buf = 0;
    for (int t = 0; t < nT; t++) {
        cpa_wait1();
        __syncthreads();
        if (t + 2 < nT) {
            int nb = buf + 2; if (nb >= 3) nb -= 3;
            tcga_issue(sb0 + nb*STAGEB, A, B, m0, Mend, n0, N, K, (t + 2)*BK, tid);
        }
        cpa_commit();

        const float* sA = smtc + (size_t)buf * (STAGEB/4);
        const float* sB = sA + 4096;
#pragma unroll
        for (int g = 0; g < 2; g++) {
            int ch = ((g*4 + tig) ^ swl) << 2;
            float4 bq[4];
#pragma unroll
            for (int j = 0; j < 4; j++)
                bq[j] = *(const float4*)&sB[(wn + j*8 + grp)*32 + ch];
#pragma unroll
            for (int i = 0; i < 4; i++) {
                int ra = (wm + i*16 + grp)*32 + ch;
                float4 alo = *(const float4*)&sA[ra];
                float4 ahi = *(const float4*)&sA[ra + 8*32];
#pragma unroll
                for (int j = 0; j < 4; j++) {
                    mma_tf32(acc[i][j], make_float2(alo.x, alo.y),
                             make_float2(ahi.x, ahi.y), make_float2(bq[j].x, bq[j].y));
                    mma_tf32(acc[i][j], make_float2(alo.z, alo.w),
                             make_float2(ahi.z, ahi.w), make_float2(bq[j].z, bq[j].w));
                }
            }
        }
        buf = (buf == 2) ? 0 : buf + 1;
    }

#pragma unroll
    for (int i = 0; i < 4; i++) {
#pragma unroll
        for (int j = 0; j < 4; j++) {
#pragma unroll
            for (int half = 0; half < 2; half++) {
                int row = m0 + wm + i*16 + grp + half*8;
                int col = n0 + wn + j*8 + tig*2;
                if (row >= Mend || col >= N) continue;
                float a0 = acc[i][j][2*half+0]*TRUNC_COMP;
                float a1 = acc[i][j][2*half+1]*TRUNC_COMP;
                float2 v = make_float2(a0, a1);
                if (R) { v.x += R[(size_t)row*N + col]; v.y += R[(size_t)row*N + col+1]; }
                *(float2*)(C + (size_t)row*N + col) = v;
            }
        }
    }
}

__global__ __launch_bounds__(256, 2) void gemm_tf32_kernel(
    const float* __restrict__ A, const float* __restrict__ B,
    float* __restrict__ C, const float* __restrict__ R, int M, int N, int K) {
    gemm_tf32_body(A, B, C, R, blockIdx.y*BM, M, blockIdx.x*BN, N, K);
}

__global__ __launch_bounds__(256, 2) void gemm_qkv_kernel(
    const float* __restrict__ A,
    const float* __restrict__ wq, const float* __restrict__ wk, const float* __restrict__ wv) {
    int nb = blockIdx.x;
    const float* B; float* C; int n0, N;
    if (nb < 16)      { B = wq; C = g_q; n0 = nb*BN;       N = NHEAD*HD; }
    else if (nb < 20) { B = wk; C = g_k; n0 = (nb-16)*BN;  N = NKVH*HD;  }
    else              { B = wv; C = g_v; n0 = (nb-20)*BN;  N = NKVH*HD;  }
    gemm_tf32_body(A, B, C, nullptr, blockIdx.y*BM, SQ, n0, N, HDIM);
}

__global__ __launch_bounds__(256, 2) void gemm_tf32_group_kernel(
    const float* __restrict__ A, const float* __restrict__ Ball,
    float* __restrict__ C, int N, int K) {
    int e = blockIdx.z;
    int mstart = g_off[e], mend = g_off[e+1];
    int m0 = mstart + blockIdx.y*BM;
    if (m0 >= mend) return;
    gemm_tf32_body(A, Ball + (size_t)e*N*K, C, nullptr, m0, mend, blockIdx.x*BN, N, K);
}

// ---------------- Fused w1+w3 grouped GEMM with silu epilogue ----------------
__device__ __forceinline__ void w13_issue(
    unsigned sbase, const float* __restrict__ A,
    const float* __restrict__ B1, const float* __restrict__ B3,
    int m0, int Mend, int n0, int K, int ks, int tid)
{
#pragma unroll
    for (int i = 0; i < 8; i++) {
        int idx = tid + i*256;
        int isB = idx >> 10;
        int l = idx & 1023;
        int r = l >> 3, c = l & 7;
        const float* src;
        int bytes = 16;
        if (!isB) {
            src = A + (size_t)(m0 + r)*K + ks + (c << 2);
            if (m0 + r >= Mend) bytes = 0;
        } else {
            const float* Bsel = (r < 64) ? B1 : B3;
            src = Bsel + (size_t)(n0 + (r & 63))*K + ks + (c << 2);
        }
        int csw = c ^ ((r & 1) << 2);
        unsigned dst = sbase + (isB ? 16384u : 0u) + (unsigned)(r*128 + csw*16);
        cpa16(dst, src, bytes);
    }
}

__global__ __launch_bounds__(256, 2) void gemm_w13silu_group_kernel(
    const float* __restrict__ A, const float* __restrict__ W1all,
    const float* __restrict__ W3all, float* __restrict__ b1out) {
    int e = blockIdx.z;
    int mstart = g_off[e], mend = g_off[e+1];
    int m0 = mstart + blockIdx.y*BM;
    if (m0 >= mend) return;
    int n0 = blockIdx.x * 64;
    const float* B1 = W1all + (size_t)e*IDIM*HDIM;
    const float* B3 = W3all + (size_t)e*IDIM*HDIM;
    const int K = HDIM;

    extern __shared__ float smtc[];
    unsigned sb0 = smem_u32(smtc);
    int tid = threadIdx.x;
    int lane = tid & 31, wid = tid >> 5;
    int wm = (wid & 1) * 64;
    int wn = (wid >> 1) * 16;
    int tig = lane & 3, grp = lane >> 2;
    int swl = (grp & 1) << 2;

    float acc1[4][2][4], acc3[4][2][4];
#pragma unroll
    for (int i = 0; i < 4; i++)
#pragma unroll
        for (int j = 0; j < 2; j++)
#pragma unroll
            for (int r = 0; r < 4; r++) { acc1[i][j][r] = 0.f; acc3[i][j][r] = 0.f; }

    int nT = K / BK;
    w13_issue(sb0,          A, B1, B3, m0, mend, n0, K, 0,  tid); cpa_commit();
    w13_issue(sb0 + STAGEB, A, B1, B3, m0, mend, n0, K, BK, tid); cpa_commit();

    int buf = 0;
    for (int t = 0; t < nT; t++) {
        cpa_wait1();
        __syncthreads();
        if (t + 2 < nT) {
            int nb = buf + 2; if (nb >= 3) nb -= 3;
            w13_issue(sb0 + nb*STAGEB, A, B1, B3, m0, mend, n0, K, (t + 2)*BK, tid);
        }
        cpa_commit();

        const float* sA = smtc + (size_t)buf * (STAGEB/4);
        const float* sB = sA + 4096;
#pragma unroll
        for (int g = 0; g < 2; g++) {
            int ch = ((g*4 + tig) ^ swl) << 2;
            float4 b1q[2], b3q[2];
#pragma unroll
            for (int j = 0; j < 2; j++) {
                b1q[j] = *(const float4*)&sB[(wn + j*8 + grp)*32 + ch];
                b3q[j] = *(const float4*)&sB[(64 + wn + j*8 + grp)*32 + ch];
            }
#pragma unroll
            for (int i = 0; i < 4; i++) {
                int ra = (wm + i*16 + grp)*32 + ch;
                float4 alo = *(const float4*)&sA[ra];
                float4 ahi = *(const float4*)&sA[ra + 8*32];
#pragma unroll
                for (int j = 0; j < 2; j++) {
                    mma_tf32(acc1[i][j], make_float2(alo.x, alo.y),
                             make_float2(ahi.x, ahi.y), make_float2(b1q[j].x, b1q[j].y));
                    mma_tf32(acc1[i][j], make_float2(alo.z, alo.w),
                             make_float2(ahi.z, ahi.w), make_float2(b1q[j].z, b1q[j].w));
                    mma_tf32(acc3[i][j], make_float2(alo.x, alo.y),
                             make_float2(ahi.x, ahi.y), make_float2(b3q[j].x, b3q[j].y));
                    mma_tf32(acc3[i][j], make_float2(alo.z, alo.w),
                             make_float2(ahi.z, ahi.w), make_float2(b3q[j].z, b3q[j].w));
                }
            }
        }
        buf = (buf == 2) ? 0 : buf + 1;
    }

#pragma unroll
    for (int i = 0; i < 4; i++) {
#pragma unroll
        for (int j = 0; j < 2; j++) {
#pragma unroll
            for (int half = 0; half < 2; half++) {
                int row = m0 + wm + i*16 + grp + half*8;
                if (row >= mend) continue;
                int col = n0 + wn + j*8 + tig*2;
                float v1a = acc1[i][j][2*half+0]*TRUNC_COMP;
                float v1b = acc1[i][j][2*half+1]*TRUNC_COMP;
                float v3a = acc3[i][j][2*half+0]*TRUNC_COMP;
                float v3b = acc3[i][j][2*half+1]*TRUNC_COMP;
                float ga = v1a / (1.f + __expf(-v1a));
                float gb = v1b / (1.f + __expf(-v1b));
                float2 v = make_float2(f2tf32rn(ga*v3a), f2tf32rn(gb*v3b));
                *(float2*)(b1out + (size_t)row*IDIM + col) = v;
            }
        }
    }
}

// ------------------------- RoPE (in-place, outputs tf32-rounded) -------------------------
__global__ void rope_kernel(float* __restrict__ q, float* __restrict__ k) {
    int s  = blockIdx.x;
    int hh = blockIdx.y;
    int d2 = threadIdx.x;
    float* p;
    if (hh < NHEAD) p = q + (size_t)s*(NHEAD*HD) + hh*HD;
    else            p = k + (size_t)s*(NKVH*HD) + (hh-NHEAD)*HD;
    float ps = g_posf[s];
    float inv = exp2f(-(float)d2 * 0.41524101186092029f);
    float ang = ps * inv;
    float sn, cs;
    sincosf(ang, &sn, &cs);
    float x1 = p[d2], x2 = p[d2+32];
    p[d2]    = f2tf32rn(x1*cs - x2*sn);
    p[d2+32] = f2tf32rn(x2*cs + x1*sn);
}

// ------------------------- Flash attention on tf32 mma.sync -------------------------
#define AQT 128
#define AKT 32

__global__ __launch_bounds__(256) void attn_mma_kernel(
    const float* __restrict__ q, const float* __restrict__ k,
    const float* __restrict__ v, float* __restrict__ ctx)
{
    __shared__ float sm[8192];
    int bq = gridDim.x - 1 - blockIdx.x;   // heavy tiles first
    int h = blockIdx.y;
    int kvh = h >> 2;
    int q0 = bq * AQT;
    int tid = threadIdx.x, wid = tid >> 5, lane = tid & 31;
    int tig = lane & 3, grp = lane >> 2;

#pragma unroll
    for (int i = 0; i < 8; i++) {
        int fid = tid + i*256;
        int row = fid >> 4, c4 = fid & 15;
        float4 vq = *(const float4*)(q + (size_t)(q0+row)*(NHEAD*HD) + h*HD + (c4 << 2));
        int g = c4 >> 2, sw = (row & 3) ^ ((row >> 2) & 1);
        float* d = &sm[row*64 + g*16 + (c4 & 3)];
        d[((0^sw)<<2)] = vq.x; d[((1^sw)<<2)] = vq.y;
        d[((2^sw)<<2)] = vq.z; d[((3^sw)<<2)] = vq.w;
    }
    __syncthreads();
    int r0 = wid*16 + grp;
    int swA = (grp & 3) ^ ((grp >> 2) & 1);
    int chA = ((tig ^ swA) << 2);
    float4 qf0[4], qf1[4];
#pragma unroll
    for (int g = 0; g < 4; g++) {
        qf0[g] = *(const float4*)&sm[r0*64 + g*16 + chA];
        qf1[g] = *(const float4*)&sm[(r0+8)*64 + g*16 + chA];
    }
    __syncthreads();

    int qrow0 = q0 + r0, qrow1 = qrow0 + 8;
    float m0 = -INFINITY, m1 = -INFINITY, l0 = 0.f, l1 = 0.f;
    float oa[8][4];
#pragma unroll
    for (int j = 0; j < 8; j++)
#pragma unroll
        for (int r = 0; r < 4; r++) oa[j][r] = 0.f;

    float* pslab = &sm[4096 + wid*512];
    int chP = chA;

    int nkt = 4*bq + 4;
    for (int kt = 0; kt < nkt; kt++) {
#pragma unroll
        for (int i = 0; i < 2; i++) {
            int fid = tid + i*256;
            int row = fid >> 4, c4 = fid & 15;
            size_t goff = (size_t)(kt*AKT + row)*(NKVH*HD) + kvh*HD + (c4 << 2);
            float4 kv4 = *(const float4*)(k + goff);
            int g = c4 >> 2, sw = (row & 3) ^ ((row >> 2) & 1);
            float* d = &sm[row*64 + g*16 + (c4 & 3)];
            d[((0^sw)<<2)] = kv4.x; d[((1^sw)<<2)] = kv4.y;
            d[((2^sw)<<2)] = kv4.z; d[((3^sw)<<2)] = kv4.w;
            float4 vv4 = *(const float4*)(v + goff);
            float vals[4] = {vv4.x, vv4.y, vv4.z, vv4.w};
            int k16 = row & 15;
            int cbase = (row >> 4)*16 + (k16 >> 2);
#pragma unroll
            for (int e = 0; e < 4; e++) {
                int dp = (c4 << 2) + e;
                int sw2 = (dp & 3) ^ ((dp >> 2) & 1);
                sm[2048 + dp*32 + cbase + (((k16 & 3) ^ sw2) << 2)] = f2tf32rn(vals[e]);
            }
        }
        __syncthreads();

        float sc[4][4];
#pragma unroll
        for (int j = 0; j < 4; j++)
#pragma unroll
            for (int r = 0; r < 4; r++) sc[j][r] = 0.f;
#pragma unroll
        for (int j = 0; j < 4; j++) {
            int krow = j*8 + grp;
            int swB = (krow & 3) ^ ((krow >> 2) & 1);
            int chB = ((tig ^ swB) << 2);
#pragma unroll
            for (int g = 0; g < 4; g++) {
                float4 bf = *(const float4*)&sm[krow*64 + g*16 + chB];
                mma_tf32(sc[j], make_float2(qf0[g].x, qf0[g].y),
                         make_float2(qf1[g].x, qf1[g].y), make_float2(bf.x, bf.y));
                mma_tf32(sc[j], make_float2(qf0[g].z, qf0[g].w),
                         make_float2(qf1[g].z, qf1[g].w), make_float2(bf.z, bf.w));
            }
        }

        float lm0 = -INFINITY, lm1 = -INFINITY;
#pragma unroll
        for (int j = 0; j < 4; j++) {
            int col = kt*AKT + j*8 + 2*tig;
            sc[j][0] = (col     <= qrow0) ? sc[j][0]*0.125f : -1e30f;
            sc[j][1] = (col + 1 <= qrow0) ? sc[j][1]*0.125f : -1e30f;
            sc[j][2] = (col     <= qrow1) ? sc[j][2]*0.125f : -1e30f;
            sc[j][3] = (col + 1 <= qrow1) ? sc[j][3]*0.125f : -1e30f;
            lm0 = fmaxf(lm0, fmaxf(sc[j][0], sc[j][1]));
            lm1 = fmaxf(lm1, fmaxf(sc[j][2], sc[j][3]));
        }
        lm0 = fmaxf(lm0, __shfl_xor_sync(0xffffffffu, lm0, 1));
        lm0 = fmaxf(lm0, __shfl_xor_sync(0xffffffffu, lm0, 2));
        lm1 = fmaxf(lm1, __shfl_xor_sync(0xffffffffu, lm1, 1));
        lm1 = fmaxf(lm1, __shfl_xor_sync(0xffffffffu, lm1, 2));
        float mn0 = fmaxf(m0, lm0), mn1 = fmaxf(m1, lm1);
        float s0 = __expf(m0 - mn0), s1 = __expf(m1 - mn1);
        float ps0 = 0.f, ps1 = 0.f;
#pragma unroll
        for (int j = 0; j < 4; j++) {
            sc[j][0] = __expf(sc[j][0] - mn0);
            sc[j][1] = __expf(sc[j][1] - mn0);
            sc[j][2] = __expf(sc[j][2] - mn1);
            sc[j][3] = __expf(sc[j][3] - mn1);
            ps0 += sc[j][0] + sc[j][1];
            ps1 += sc[j][2] + sc[j][3];
        }
        ps0 += __shfl_xor_sync(0xffffffffu, ps0, 1);
        ps0 += __shfl_xor_sync(0xffffffffu, ps0, 2);
        ps1 += __shfl_xor_sync(0xffffffffu, ps1, 1);
        ps1 += __shfl_xor_sync(0xffffffffu, ps1, 2);
        l0 = l0*s0 + ps0; l1 = l1*s1 + ps1;
        m0 = mn0; m1 = mn1;
#pragma unroll
        for (int j = 0; j < 8; j++) {
            oa[j][0] *= s0; oa[j][1] *= s0;
            oa[j][2] *= s1; oa[j][3] *= s1;
        }

#pragma unroll
        for (int j = 0; j < 4; j++) {
            int g2 = j >> 1;
            int k16a = (j & 1)*8 + 2*tig;
            int k16b = k16a + 1;
            int c0 = g2*16 + (((k16a & 3) ^ swA) << 2) + (k16a >> 2);
            int c1 = g2*16 + (((k16b & 3) ^ swA) << 2) + (k16b >> 2);
            pslab[grp*32 + c0]     = f2tf32rn(sc[j][0]);
            pslab[grp*32 + c1]     = f2tf32rn(sc[j][1]);
            pslab[(grp+8)*32 + c0] = f2tf32rn(sc[j][2]);
            pslab[(grp+8)*32 + c1] = f2tf32rn(sc[j][3]);
        }
        __syncwarp();
        float4 pf0[2], pf1[2];
#pragma unroll
        for (int g = 0; g < 2; g++) {
            pf0[g] = *(const float4*)&pslab[grp*32 + g*16 + chP];
            pf1[g] = *(const float4*)&pslab[(grp+8)*32 + g*16 + chP];
        }

#pragma unroll
        for (int jd = 0; jd < 8; jd++) {
            int vrow = jd*8 + grp;
            int swV = (vrow & 3) ^ ((vrow >> 2) & 1);
            int chV = ((tig ^ swV) << 2);
#pragma unroll
            for (int g = 0; g < 2; g++) {
                float4 bf = *(const float4*)&sm[2048 + vrow*32 + g*16 + chV];
                mma_tf32(oa[jd], make_float2(pf0[g].x, pf0[g].y),
                         make_float2(pf1[g].x, pf1[g].y), make_float2(bf.x, bf.y));
                mma_tf32(oa[jd], make_float2(pf0[g].z, pf0[g].w),
                         make_float2(pf1[g].z, pf1[g].w), make_float2(bf.z, bf.w));
            }
        }
        __syncthreads();
    }

    float rl0 = 1.f / l0, rl1 = 1.f / l1;
#pragma unroll
    for (int jd = 0; jd < 8; jd++) {
        int dcol = jd*8 + 2*tig;
        float2 v0 = make_float2(f2tf32rn(oa[jd][0]*rl0), f2tf32rn(oa[jd][1]*rl0));
        float2 v1 = make_float2(f2tf32rn(oa[jd][2]*rl1), f2tf32rn(oa[jd][3]*rl1));
        *(float2*)(ctx + (size_t)qrow0*(NHEAD*HD) + h*HD + dcol) = v0;
        *(float2*)(ctx + (size_t)qrow1*(NHEAD*HD) + h*HD + dcol) = v1;
    }
}

// ------------------------- MoE bookkeeping -------------------------
__global__ void scan_kernel() {
    if (threadIdx.x == 0) {
        int acc = 0;
        for (int e = 0; e < NE; e++) { g_off[e] = acc; acc += g_cnt[e]; }
        g_off[NE] = acc;
    }
}

__global__ void scatter_kernel() {
    int t = blockIdx.x*blockDim.x + threadIdx.x;
    if (t >= SQ) return;
#pragma unroll
    for (int sl = 0; sl < 2; sl++) {
        int e = g_tok2e[t*2+sl];
        int rrel = atomicAdd(&g_cur[e], 1);
        int rr = g_off[e] + rrel;
        g_rows[rr] = t;
        g_tok2row[t*2+sl] = rr;
    }
}

__global__ void gather_kernel() {
    int total = SQ*2*(HDIM/4);
    for (int idx = blockIdx.x*blockDim.x + threadIdx.x; idx < total; idx += gridDim.x*blockDim.x) {
        int row = idx / (HDIM/4);
        int c4  = idx % (HDIM/4);
        float4 v = ((const float4*)g_xn2)[(size_t)g_rows[row]*(HDIM/4) + c4];
        v.x = f2tf32rn(v.x); v.y = f2tf32rn(v.y);
        v.z = f2tf32rn(v.z); v.w = f2tf32rn(v.w);
        ((float4*)g_xg)[(size_t)row*(HDIM/4) + c4] = v;
    }
}

__global__ void finalize_kernel(const float* __restrict__ resid, float* __restrict__ out) {
    int t = blockIdx.x;
    int r0 = g_tok2row[t*2], r1 = g_tok2row[t*2+1];
    float w0 = g_tok2w[t*2], w1 = g_tok2w[t*2+1];
    for (int c = threadIdx.x; c < HDIM; c += blockDim.x) {
        out[(size_t)t*HDIM + c] = resid[(size_t)t*HDIM + c]
            + w0*g_y[(size_t)r0*HDIM + c] + w1*g_y[(size_t)r1*HDIM + c];
    }
}

// ------------------------- output tail writers -------------------------
__global__ void gate_kernel(float* __restrict__ dst, const float* __restrict__ gin) {
    int i = blockIdx.x*blockDim.x + threadIdx.x;
    int total = 4*SQ*NE;
    if (i < total) dst[i] = (i < SQ*NE) ? g_rlog[i] : gin[i];
}

__global__ void posf_kernel(float* __restrict__ dst, int n) {
    int i = blockIdx.x*blockDim.x + threadIdx.x;
    if (i < n) dst[i] = g_posf[i];
}

__global__ void posraw_kernel(float* __restrict__ dst, int n) {
    int i = blockIdx.x*blockDim.x + threadIdx.x;
    if (i < n) ((long long*)dst)[i] = (long long)g_posf[i];
}

__global__ void zerofill_kernel(float* __restrict__ dst, int n) {
    int i = blockIdx.x*blockDim.x + threadIdx.x;
    if (i < n) dst[i] = 0.f;
}

// ------------------------- launch -------------------------
extern "C" void kernel_launch(void* const* d_in, const int* in_sizes, int n_in,
                              void* d_out, int out_size) {
    const float* hidden = (const float*)d_in[0];
    const void*  posraw = d_in[1];
    const float* gatein = (const float*)d_in[2];
    const float* ln1 = (const float*)d_in[3];
    const float* ln2 = (const float*)d_in[4];
    const float* wq  = (const float*)d_in[5];
    const float* wk  = (const float*)d_in[6];
    const float* wv  = (const float*)d_in[7];
    const float* wo  = (const float*)d_in[8];
    const float* wg  = (const float*)d_in[9];
    const float* w1  = (const float*)d_in[10];
    const float* w2  = (const float*)d_in[11];
    const float* w3  = (const float*)d_in[12];

    float *xn1,*q,*k,*v,*ctx,*resid1,*xn2,*xg,*b1,*y;
    cudaGetSymbolAddress((void**)&xn1,    g_xn1);
    cudaGetSymbolAddress((void**)&q,      g_q);
    cudaGetSymbolAddress((void**)&k,      g_k);
    cudaGetSymbolAddress((void**)&v,      g_v);
    cudaGetSymbolAddress((void**)&ctx,    g_ctx);
    cudaGetSymbolAddress((void**)&resid1, g_resid1);
    cudaGetSymbolAddress((void**)&xn2,    g_xn2);
    cudaGetSymbolAddress((void**)&xg,     g_xg);
    cudaGetSymbolAddress((void**)&b1,     g_b1);
    cudaGetSymbolAddress((void**)&y,      g_y);

    cudaFuncSetAttribute(gemm_tf32_kernel,          cudaFuncAttributeMaxDynamicSharedMemorySize, SMEMTC);
    cudaFuncSetAttribute(gemm_qkv_kernel,           cudaFuncAttributeMaxDynamicSharedMemorySize, SMEMTC);
    cudaFuncSetAttribute(gemm_tf32_group_kernel,    cudaFuncAttributeMaxDynamicSharedMemorySize, SMEMTC);
    cudaFuncSetAttribute(gemm_w13silu_group_kernel, cudaFuncAttributeMaxDynamicSharedMemorySize, SMEMTC);

    posdetect_kernel<<<1, 256>>>((const unsigned int*)posraw);
    posconv_kernel<<<SQ/256, 256>>>(posraw);

    // attention path
    rmsnorm_kernel<<<SQ, 256>>>(hidden, ln1, xn1);
    gemm_qkv_kernel<<<dim3(24, SQ/BM), 256, SMEMTC>>>(xn1, wq, wk, wv);
    rope_kernel<<<dim3(SQ, NHEAD+NKVH), 32>>>(q, k);
    attn_mma_kernel<<<dim3(SQ/AQT, NHEAD), 256>>>(q, k, v, ctx);
    dim3 gq(HDIM/BN, SQ/BM);
    gemm_tf32_kernel<<<gq, 256, SMEMTC>>>(ctx, wo, resid1, hidden, SQ, HDIM, HDIM);

    // MoE path (rmsnorm-2 fused with router)
    rmsnorm_router_kernel<<<SQ, 256>>>(resid1, ln2, xn2, wg);
    scan_kernel<<<1, 32>>>();
    scatter_kernel<<<SQ/256, 256>>>();
    gather_kernel<<<512, 256>>>();
    gemm_w13silu_group_kernel<<<dim3(IDIM/64, SQ/BM, NE), 256, SMEMTC>>>(xg, w1, w3, b1);
    gemm_tf32_group_kernel<<<dim3(HDIM/BN, SQ/BM, NE), 256, SMEMTC>>>(b1, w2, y, HDIM, IDIM);

    float* out = (float*)d_out;
    const int HTOT = SQ*HDIM;
    const int GTOT = 4*SQ*NE;
    finalize_kernel<<<SQ, 256>>>(resid1, out);

    int rem = out_size - HTOT;
    if (rem >= GTOT) {
        gate_kernel<<<(GTOT+255)/256, 256>>>(out + (out_size - GTOT), gatein);
        rem -= GTOT;
    }
    if (rem == SQ) {
        posf_kernel<<<(SQ+255)/256, 256>>>(out + HTOT, SQ);
    } else if (rem == 2*SQ) {
        posraw_kernel<<<(SQ+255)/256, 256>>>(out + HTOT, SQ);
    } else if (rem > 0) {
        zerofill_kernel<<<(rem+255)/256, 256>>>(out + HTOT, rem);
    }
}